// round 1
// baseline (speedup 1.0000x reference)
#include <cuda_runtime.h>
#include <math.h>

#define N_TOK   8192
#define D_MODEL 1024
#define N_EXP   8
#define RANK    16
#define H_COLS  (N_EXP * RANK)               // 128
#define NCAT    (N_EXP + D_MODEL + H_COLS)   // 1160

// Scratch (allocation-free rule: __device__ globals)
__device__ float g_Wcat[D_MODEL * NCAT];     // [k=1024][j=1160] row-major
__device__ float g_logits[N_TOK * N_EXP];
__device__ float g_h[N_TOK * H_COLS];
__device__ float g_c[N_TOK * N_EXP];         // dense combine weights

// ---------------------------------------------------------------------------
// Pack [W_gate^T | W_base^T | A_flat] into g_Wcat (k-major rows of 1160)
// ---------------------------------------------------------------------------
__global__ void pack_wcat(const float* __restrict__ Wg,
                          const float* __restrict__ A,
                          const float* __restrict__ Wb) {
    int idx = blockIdx.x * blockDim.x + threadIdx.x;
    if (idx >= D_MODEL * NCAT) return;
    int k = idx / NCAT;
    int j = idx - k * NCAT;
    float v;
    if (j < N_EXP) {
        v = Wg[j * D_MODEL + k];                       // W_gate[e][k]
    } else if (j < N_EXP + D_MODEL) {
        v = Wb[(j - N_EXP) * D_MODEL + k];             // W_base[d][k]
    } else {
        int jj = j - (N_EXP + D_MODEL);
        int e = jj >> 4, r = jj & 15;
        v = A[((e * D_MODEL) + k) * RANK + r];         // A[e][k][r]
    }
    g_Wcat[idx] = v;
}

// ---------------------------------------------------------------------------
// GEMM A: C[N_TOK, NCAT] = x[N_TOK, 1024] @ g_Wcat[1024, NCAT]
// 128x128 tile, BK=16, 256 threads, 8x8 per thread. Epilogue routes columns.
// ---------------------------------------------------------------------------
__global__ __launch_bounds__(256)
void gemm_fused(const float* __restrict__ x,
                const float* __restrict__ b_base,
                float* __restrict__ out) {
    __shared__ __align__(16) float As[16][128];
    __shared__ __align__(16) float Bs[16][128];

    const int n0 = blockIdx.x * 128;
    const int m0 = blockIdx.y * 128;
    const int tid = threadIdx.x;
    const int tx = tid & 15;        // col group
    const int ty = tid >> 4;        // row group

    float acc[8][8];
#pragma unroll
    for (int i = 0; i < 8; i++)
#pragma unroll
        for (int j = 0; j < 8; j++) acc[i][j] = 0.f;

    for (int kt = 0; kt < D_MODEL; kt += 16) {
        // Load x tile (128 rows x 16 k), transpose into As[k][m]
#pragma unroll
        for (int it = 0; it < 2; it++) {
            int id = tid + it * 256;        // 512 float4 total
            int row = id >> 2;
            int c4 = (id & 3) * 4;
            float4 v = *(const float4*)(x + (size_t)(m0 + row) * D_MODEL + kt + c4);
            As[c4 + 0][row] = v.x;
            As[c4 + 1][row] = v.y;
            As[c4 + 2][row] = v.z;
            As[c4 + 3][row] = v.w;
        }
        // Load Wcat tile (16 k x 128 cols) into Bs[k][n] (guard tail cols)
#pragma unroll
        for (int it = 0; it < 2; it++) {
            int id = tid + it * 256;
            int r = id >> 5;
            int c4 = (id & 31) * 4;
            int col = n0 + c4;
            float4 v = make_float4(0.f, 0.f, 0.f, 0.f);
            if (col < NCAT)
                v = *(const float4*)(g_Wcat + (size_t)(kt + r) * NCAT + col);
            *(float4*)&Bs[r][c4] = v;
        }
        __syncthreads();

#pragma unroll
        for (int k = 0; k < 16; k++) {
            float a[8], b[8];
#pragma unroll
            for (int i = 0; i < 8; i++) a[i] = As[k][ty * 8 + i];
#pragma unroll
            for (int j = 0; j < 8; j++) b[j] = Bs[k][tx * 8 + j];
#pragma unroll
            for (int i = 0; i < 8; i++)
#pragma unroll
                for (int j = 0; j < 8; j++) acc[i][j] = fmaf(a[i], b[j], acc[i][j]);
        }
        __syncthreads();
    }

    // Epilogue: route columns (logits | base+bias -> out | h)
#pragma unroll
    for (int i = 0; i < 8; i++) {
        int m = m0 + ty * 8 + i;
#pragma unroll
        for (int j = 0; j < 8; j++) {
            int col = n0 + tx * 8 + j;
            float v = acc[i][j];
            if (col < N_EXP) {
                g_logits[m * N_EXP + col] = v;
            } else if (col < N_EXP + D_MODEL) {
                int d = col - N_EXP;
                out[(size_t)m * D_MODEL + d] = v + b_base[d];
            } else if (col < NCAT) {
                g_h[m * H_COLS + (col - (N_EXP + D_MODEL))] = v;
            }
        }
    }
}

// ---------------------------------------------------------------------------
// Gate: per-token top-2 over 8 logits, softmax over the 2, dense combine
// Tie-break: lowest index first (matches jax.lax.top_k)
// ---------------------------------------------------------------------------
__global__ void gate_kernel() {
    int n = blockIdx.x * blockDim.x + threadIdx.x;
    if (n >= N_TOK) return;
    float l[N_EXP];
#pragma unroll
    for (int e = 0; e < N_EXP; e++) l[e] = g_logits[n * N_EXP + e];

    int i0 = 0; float v0 = l[0];
#pragma unroll
    for (int e = 1; e < N_EXP; e++) if (l[e] > v0) { v0 = l[e]; i0 = e; }
    int i1 = -1; float v1 = -1e30f;
#pragma unroll
    for (int e = 0; e < N_EXP; e++) if (e != i0 && l[e] > v1) { v1 = l[e]; i1 = e; }

    // softmax over [v0, v1] with v0 >= v1
    float e1 = expf(v1 - v0);
    float inv = 1.0f / (1.0f + e1);
    float w0 = inv;
    float w1 = e1 * inv;

#pragma unroll
    for (int e = 0; e < N_EXP; e++) {
        float c = (e == i0) ? w0 : (e == i1) ? w1 : 0.f;
        g_c[n * N_EXP + e] = c;
    }
}

// ---------------------------------------------------------------------------
// GEMM C: out += (scaled h)[N_TOK, 128] @ B[128, 1024]
// combine scaling fused into A-tile load. All dims divide tiles exactly.
// ---------------------------------------------------------------------------
__global__ __launch_bounds__(256)
void gemm_lora_up(const float* __restrict__ Bmat,
                  float* __restrict__ out) {
    __shared__ __align__(16) float As[16][128];
    __shared__ __align__(16) float Bs[16][128];

    const int n0 = blockIdx.x * 128;
    const int m0 = blockIdx.y * 128;
    const int tid = threadIdx.x;
    const int tx = tid & 15;
    const int ty = tid >> 4;

    float acc[8][8];
#pragma unroll
    for (int i = 0; i < 8; i++)
#pragma unroll
        for (int j = 0; j < 8; j++) acc[i][j] = 0.f;

    for (int kt = 0; kt < H_COLS; kt += 16) {
#pragma unroll
        for (int it = 0; it < 2; it++) {
            int id = tid + it * 256;
            int row = id >> 2;
            int c4 = (id & 3) * 4;
            int kg = kt + c4;                 // global k, 4-aligned within one expert block of 16
            int e = kg >> 4;
            float s = g_c[(m0 + row) * N_EXP + e];
            float4 v = *(const float4*)(g_h + (size_t)(m0 + row) * H_COLS + kg);
            As[c4 + 0][row] = v.x * s;
            As[c4 + 1][row] = v.y * s;
            As[c4 + 2][row] = v.z * s;
            As[c4 + 3][row] = v.w * s;
        }
#pragma unroll
        for (int it = 0; it < 2; it++) {
            int id = tid + it * 256;
            int r = id >> 5;
            int c4 = (id & 31) * 4;
            float4 v = *(const float4*)(Bmat + (size_t)(kt + r) * D_MODEL + n0 + c4);
            *(float4*)&Bs[r][c4] = v;
        }
        __syncthreads();

#pragma unroll
        for (int k = 0; k < 16; k++) {
            float a[8], b[8];
#pragma unroll
            for (int i = 0; i < 8; i++) a[i] = As[k][ty * 8 + i];
#pragma unroll
            for (int j = 0; j < 8; j++) b[j] = Bs[k][tx * 8 + j];
#pragma unroll
            for (int i = 0; i < 8; i++)
#pragma unroll
                for (int j = 0; j < 8; j++) acc[i][j] = fmaf(a[i], b[j], acc[i][j]);
        }
        __syncthreads();
    }

#pragma unroll
    for (int i = 0; i < 8; i++) {
        int m = m0 + ty * 8 + i;
#pragma unroll
        for (int j = 0; j < 8; j++) {
            int col = n0 + tx * 8 + j;
            size_t o = (size_t)m * D_MODEL + col;
            out[o] += acc[i][j];
        }
    }
}

// ---------------------------------------------------------------------------
extern "C" void kernel_launch(void* const* d_in, const int* in_sizes, int n_in,
                              void* d_out, int out_size) {
    const float* x      = (const float*)d_in[0];
    const float* W_gate = (const float*)d_in[1];
    const float* A      = (const float*)d_in[2];
    const float* Bmat   = (const float*)d_in[3];
    const float* W_base = (const float*)d_in[4];
    const float* b_base = (const float*)d_in[5];
    float* out = (float*)d_out;

    pack_wcat<<<(D_MODEL * NCAT + 255) / 256, 256>>>(W_gate, A, W_base);

    dim3 gridA((NCAT + 127) / 128, N_TOK / 128);   // (10, 64)
    gemm_fused<<<gridA, 256>>>(x, b_base, out);

    gate_kernel<<<N_TOK / 256, 256>>>();

    dim3 gridC(D_MODEL / 128, N_TOK / 128);        // (8, 64)
    gemm_lora_up<<<gridC, 256>>>(Bmat, out);
}

// round 5
// speedup vs baseline: 5.4390x; 5.4390x over previous
#include <cuda_runtime.h>
#include <cuda_fp16.h>
#include <cstdint>
#include <math.h>

#define N_TOK   8192
#define D_MODEL 1024
#define N_EXP   8
#define RANK    16
#define H_COLS  128
#define NCAT2   (D_MODEL + H_COLS)   // 1152 = 9 * 128

// ---------------- device scratch (no-alloc rule) ----------------
__device__ __align__(16) __half g_xh[N_TOK * D_MODEL];      // x as fp16
__device__ __align__(16) __half g_wh[NCAT2 * D_MODEL];      // [Wbase^T | A] fp16, [j][k]
__device__ __align__(16) __half g_bthi[D_MODEL * H_COLS];   // B^T hi fp16 [d][r]
__device__ __align__(16) __half g_btlo[D_MODEL * H_COLS];   // B^T lo fp16 [d][r]
__device__ __align__(16) float  g_h[N_TOK * H_COLS];        // lora hidden, fp32
__device__ __align__(16) float  g_c[N_TOK * N_EXP];         // dense combine weights

// ---------------- small asm helpers (all legal at compute_103) ----------------
__device__ __forceinline__ uint32_t smem_u32(const void* p) {
    uint32_t a;
    asm("{ .reg .u64 t; cvta.to.shared.u64 t, %1; cvt.u32.u64 %0, t; }" : "=r"(a) : "l"(p));
    return a;
}
__device__ __forceinline__ void cp16(uint32_t s, const void* g) {
    asm volatile("cp.async.cg.shared.global [%0], [%1], 16;" :: "r"(s), "l"(g));
}
__device__ __forceinline__ void cp_commit() {
    asm volatile("cp.async.commit_group;" ::: "memory");
}
template<int N> __device__ __forceinline__ void cp_wait() {
    asm volatile("cp.async.wait_group %0;" :: "n"(N) : "memory");
}
__device__ __forceinline__ void ldm4(uint32_t (&r)[4], uint32_t a) {
    asm volatile("ldmatrix.sync.aligned.m8n8.x4.shared.b16 {%0,%1,%2,%3}, [%4];"
        : "=r"(r[0]), "=r"(r[1]), "=r"(r[2]), "=r"(r[3]) : "r"(a));
}
__device__ __forceinline__ void mma16816(float* c, const uint32_t* a, const uint32_t* b) {
    asm volatile("mma.sync.aligned.m16n8k16.row.col.f32.f16.f16.f32 "
        "{%0,%1,%2,%3}, {%4,%5,%6,%7}, {%8,%9}, {%0,%1,%2,%3};"
        : "+f"(c[0]), "+f"(c[1]), "+f"(c[2]), "+f"(c[3])
        : "r"(a[0]), "r"(a[1]), "r"(a[2]), "r"(a[3]), "r"(b[0]), "r"(b[1]));
}
__device__ __forceinline__ uint32_t h2u(__half2 h) { return *reinterpret_cast<uint32_t*>(&h); }

// ---------------------------------------------------------------------------
// Pack kernels
// ---------------------------------------------------------------------------
__global__ void pack_xh(const float* __restrict__ x) {
    int i = blockIdx.x * blockDim.x + threadIdx.x;          // float4 index
    if (i >= N_TOK * D_MODEL / 4) return;
    float4 v = reinterpret_cast<const float4*>(x)[i];
    uint2 u;
    u.x = h2u(__floats2half2_rn(v.x, v.y));
    u.y = h2u(__floats2half2_rn(v.z, v.w));
    reinterpret_cast<uint2*>(g_xh)[i] = u;
}

__global__ void pack_wh(const float* __restrict__ A, const float* __restrict__ Wb) {
    int idx = blockIdx.x * blockDim.x + threadIdx.x;
    if (idx >= NCAT2 * D_MODEL) return;
    int j = idx >> 10, k = idx & 1023;
    float v;
    if (j < D_MODEL) v = Wb[j * D_MODEL + k];
    else {
        int jj = j - D_MODEL;
        v = A[((size_t)((jj >> 4) * D_MODEL) + k) * RANK + (jj & 15)];
    }
    g_wh[idx] = __float2half_rn(v);
}

__global__ void pack_bt(const float* __restrict__ Bmat) {
    int idx = blockIdx.x * blockDim.x + threadIdx.x;
    if (idx >= D_MODEL * H_COLS) return;
    int d = idx >> 7, r = idx & 127;
    float v = Bmat[(size_t)r * D_MODEL + d];
    __half h = __float2half_rn(v);
    g_bthi[idx] = h;
    g_btlo[idx] = __float2half_rn(v - __half2float(h));
}

// ---------------------------------------------------------------------------
// Gate: fp32 logits (accuracy-critical), top-2 + softmax -> dense combine
// 4 tokens per warp to amortize W_gate loads. Tie-break: lowest index.
// ---------------------------------------------------------------------------
__global__ __launch_bounds__(256)
void gate_kernel(const float* __restrict__ x, const float* __restrict__ Wg) {
    const int wid = threadIdx.x >> 5, l = threadIdx.x & 31;
    const int t0 = (blockIdx.x * 8 + wid) * 4;
    float acc[4][8];
#pragma unroll
    for (int t = 0; t < 4; t++)
#pragma unroll
        for (int e = 0; e < 8; e++) acc[t][e] = 0.f;

    for (int i = 0; i < 32; i++) {
        int k = i * 32 + l;
        float wv[8];
#pragma unroll
        for (int e = 0; e < 8; e++) wv[e] = Wg[e * D_MODEL + k];
#pragma unroll
        for (int t = 0; t < 4; t++) {
            float xv = x[(size_t)(t0 + t) * D_MODEL + k];
#pragma unroll
            for (int e = 0; e < 8; e++) acc[t][e] = fmaf(xv, wv[e], acc[t][e]);
        }
    }
#pragma unroll
    for (int o = 16; o; o >>= 1)
#pragma unroll
        for (int t = 0; t < 4; t++)
#pragma unroll
            for (int e = 0; e < 8; e++)
                acc[t][e] += __shfl_xor_sync(0xffffffffu, acc[t][e], o);

    if (l == 0) {
#pragma unroll
        for (int t = 0; t < 4; t++) {
            float* lg = acc[t];
            int i0 = 0; float v0 = lg[0];
#pragma unroll
            for (int e = 1; e < 8; e++) if (lg[e] > v0) { v0 = lg[e]; i0 = e; }
            int i1 = -1; float v1 = -1e30f;
#pragma unroll
            for (int e = 0; e < 8; e++) if (e != i0 && lg[e] > v1) { v1 = lg[e]; i1 = e; }
            float e1 = expf(v1 - v0);
            float inv = 1.0f / (1.0f + e1);
#pragma unroll
            for (int e = 0; e < 8; e++)
                g_c[(size_t)(t0 + t) * N_EXP + e] = (e == i0) ? inv : (e == i1) ? e1 * inv : 0.f;
        }
    }
}

// ---------------------------------------------------------------------------
// Main GEMM: C[8192, 1152] = x_h @ Wcat_h^T  (fp16 mma.sync, 1 pass)
// CTA 128x128, BK=32 halves, 8 warps (2M x 4N), cp.async double buffer.
// Epilogue: bx<8 -> out + bias ; bx==8 -> g_h (fp32)
// Swizzle for 64B rows: chunk' = c ^ ((r>>1)&3)
// ---------------------------------------------------------------------------
#define SWA(r, c) ((uint32_t)((r) * 64 + (((c) ^ (((r) >> 1) & 3)) << 4)))

__global__ __launch_bounds__(256, 2)
void gemm_main(const float* __restrict__ b_base, float* __restrict__ out) {
    __shared__ __align__(16) __half sA[2][128 * 32];
    __shared__ __align__(16) __half sB[2][128 * 32];
    const int tid = threadIdx.x, l = tid & 31, wid = tid >> 5;
    const int wm = wid >> 2, wn = wid & 3;
    const int m0 = blockIdx.y * 128, n0 = blockIdx.x * 128;
    const uint32_t sa0 = smem_u32(sA), sb0 = smem_u32(sB);

    float acc[4][4][4];
#pragma unroll
    for (int i = 0; i < 4; i++)
#pragma unroll
        for (int j = 0; j < 4; j++)
#pragma unroll
            for (int k = 0; k < 4; k++) acc[i][j][k] = 0.f;

    auto load_tile = [&](int st, int kt) {
#pragma unroll
        for (int p = 0; p < 2; p++) {
            int cid = tid + p * 256;          // 0..511
            int r = cid >> 2, c = cid & 3;
            uint32_t sw = SWA(r, c);
            cp16(sa0 + st * 8192 + sw, g_xh + (size_t)(m0 + r) * D_MODEL + kt + c * 8);
            cp16(sb0 + st * 8192 + sw, g_wh + (size_t)(n0 + r) * D_MODEL + kt + c * 8);
        }
    };

    load_tile(0, 0);
    cp_commit();

    const int NIT = D_MODEL / 32;
    for (int it = 0; it < NIT; it++) {
        const int st = it & 1;
        if (it + 1 < NIT) { load_tile(st ^ 1, (it + 1) * 32); cp_commit(); cp_wait<1>(); }
        else              { cp_wait<0>(); }
        __syncthreads();

        const uint32_t aBase = sa0 + st * 8192;
        const uint32_t bBase = sb0 + st * 8192;
#pragma unroll
        for (int ks = 0; ks < 2; ks++) {
            uint32_t af[4][4];
#pragma unroll
            for (int mt = 0; mt < 4; mt++) {
                int row = wm * 64 + mt * 16 + (l & 15);
                int ch = ks * 2 + (l >> 4);
                ldm4(af[mt], aBase + SWA(row, ch));
            }
#pragma unroll
            for (int q = 0; q < 2; q++) {
                uint32_t bf[4];
                int rn = wn * 32 + q * 16 + ((l >> 4) << 3) + (l & 7);
                int ch = ks * 2 + ((l >> 3) & 1);
                ldm4(bf, bBase + SWA(rn, ch));
#pragma unroll
                for (int mt = 0; mt < 4; mt++) {
                    mma16816(acc[mt][q * 2],     af[mt], bf);
                    mma16816(acc[mt][q * 2 + 1], af[mt], bf + 2);
                }
            }
        }
        __syncthreads();
    }

    const bool isH = (blockIdx.x == 8);
#pragma unroll
    for (int mt = 0; mt < 4; mt++) {
        int r0 = m0 + wm * 64 + mt * 16 + (l >> 2);
#pragma unroll
        for (int nt = 0; nt < 4; nt++) {
            int j = n0 + wn * 32 + nt * 8 + (l & 3) * 2;
            float* a4 = acc[mt][nt];
            if (!isH) {
                float2 bb = *reinterpret_cast<const float2*>(b_base + j);
                float2 v0 = make_float2(a4[0] + bb.x, a4[1] + bb.y);
                float2 v1 = make_float2(a4[2] + bb.x, a4[3] + bb.y);
                *reinterpret_cast<float2*>(out + (size_t)r0 * D_MODEL + j) = v0;
                *reinterpret_cast<float2*>(out + (size_t)(r0 + 8) * D_MODEL + j) = v1;
            } else {
                int jc = j - D_MODEL;
                *reinterpret_cast<float2*>(g_h + (size_t)r0 * H_COLS + jc) =
                    make_float2(a4[0], a4[1]);
                *reinterpret_cast<float2*>(g_h + (size_t)(r0 + 8) * H_COLS + jc) =
                    make_float2(a4[2], a4[3]);
            }
        }
    }
}

// ---------------------------------------------------------------------------
// LoRA up-proj: out += (c * h)[8192,128] @ B[128,1024]
// fp16 3-pass hi/lo split (hh + hi*lo + lo*hi). K=128 single shot.
// 256B rows: chunk' = c ^ (r&7). SMEM: Ahi|Alo|Bhi|Blo = 4 x 32KB.
// ---------------------------------------------------------------------------
#define SWL(r, c) ((uint32_t)((r) * 256 + (((c) ^ ((r) & 7)) << 4)))
#define LSM_AHI 0
#define LSM_ALO 32768
#define LSM_BHI 65536
#define LSM_BLO 98304
#define LORA_SMEM 131072

__global__ __launch_bounds__(256, 1)
void gemm_lora(float* __restrict__ out) {
    extern __shared__ __align__(16) char ls[];
    const uint32_t sb = smem_u32(ls);
    const int tid = threadIdx.x, l = tid & 31, wid = tid >> 5;
    const int wm = wid >> 2, wn = wid & 3;
    const int m0 = blockIdx.y * 128, n0 = blockIdx.x * 128;

    // B tiles (pre-split fp16) via cp.async
#pragma unroll
    for (int i = 0; i < 8; i++) {
        int cid = tid + i * 256;            // 0..2047: r(128) x ch(16)
        int r = cid >> 4, ch = cid & 15;
        uint32_t sw = SWL(r, ch);
        cp16(sb + LSM_BHI + sw, g_bthi + (size_t)(n0 + r) * H_COLS + ch * 8);
        cp16(sb + LSM_BLO + sw, g_btlo + (size_t)(n0 + r) * H_COLS + ch * 8);
    }
    cp_commit();

    // A tiles: read h (fp32), scale by combine weight, split hi/lo
#pragma unroll
    for (int i = 0; i < 16; i++) {
        int fid = tid + i * 256;            // 0..4095: r(128) x c4(32)
        int r = fid >> 5, c4 = fid & 31;
        int m = m0 + r;
        float s = g_c[(size_t)m * N_EXP + (c4 >> 2)];
        float4 v = *reinterpret_cast<const float4*>(g_h + (size_t)m * H_COLS + c4 * 4);
        v.x *= s; v.y *= s; v.z *= s; v.w *= s;
        __half2 hA = __floats2half2_rn(v.x, v.y);
        __half2 hB = __floats2half2_rn(v.z, v.w);
        __half2 lA = __floats2half2_rn(v.x - __low2float(hA), v.y - __high2float(hA));
        __half2 lB = __floats2half2_rn(v.z - __low2float(hB), v.w - __high2float(hB));
        uint32_t off = SWL(r, c4 >> 1) + (c4 & 1) * 8;
        *reinterpret_cast<uint2*>(ls + LSM_AHI + off) = make_uint2(h2u(hA), h2u(hB));
        *reinterpret_cast<uint2*>(ls + LSM_ALO + off) = make_uint2(h2u(lA), h2u(lB));
    }
    cp_wait<0>();
    __syncthreads();

    float acc[4][4][4];
#pragma unroll
    for (int i = 0; i < 4; i++)
#pragma unroll
        for (int j = 0; j < 4; j++)
#pragma unroll
            for (int k = 0; k < 4; k++) acc[i][j][k] = 0.f;

#pragma unroll
    for (int pass = 0; pass < 3; pass++) {
        const uint32_t aBase = sb + (pass == 2 ? LSM_ALO : LSM_AHI);
        const uint32_t bBase = sb + (pass == 1 ? LSM_BLO : LSM_BHI);
#pragma unroll
        for (int ks = 0; ks < 8; ks++) {
            uint32_t af[4][4];
#pragma unroll
            for (int mt = 0; mt < 4; mt++) {
                int row = wm * 64 + mt * 16 + (l & 15);
                int ch = ks * 2 + (l >> 4);
                ldm4(af[mt], aBase + SWL(row, ch));
            }
#pragma unroll
            for (int q = 0; q < 2; q++) {
                uint32_t bf[4];
                int rn = wn * 32 + q * 16 + ((l >> 4) << 3) + (l & 7);
                int ch = ks * 2 + ((l >> 3) & 1);
                ldm4(bf, bBase + SWL(rn, ch));
#pragma unroll
                for (int mt = 0; mt < 4; mt++) {
                    mma16816(acc[mt][q * 2],     af[mt], bf);
                    mma16816(acc[mt][q * 2 + 1], af[mt], bf + 2);
                }
            }
        }
    }

    // epilogue: read-modify-write out
#pragma unroll
    for (int mt = 0; mt < 4; mt++) {
        int r0 = m0 + wm * 64 + mt * 16 + (l >> 2);
#pragma unroll
        for (int nt = 0; nt < 4; nt++) {
            int j = n0 + wn * 32 + nt * 8 + (l & 3) * 2;
            float* a4 = acc[mt][nt];
            float2* p0 = reinterpret_cast<float2*>(out + (size_t)r0 * D_MODEL + j);
            float2* p1 = reinterpret_cast<float2*>(out + (size_t)(r0 + 8) * D_MODEL + j);
            float2 o0 = *p0, o1 = *p1;
            o0.x += a4[0]; o0.y += a4[1];
            o1.x += a4[2]; o1.y += a4[3];
            *p0 = o0; *p1 = o1;
        }
    }
}

// ---------------------------------------------------------------------------
extern "C" void kernel_launch(void* const* d_in, const int* in_sizes, int n_in,
                              void* d_out, int out_size) {
    const float* x      = (const float*)d_in[0];
    const float* W_gate = (const float*)d_in[1];
    const float* A      = (const float*)d_in[2];
    const float* Bmat   = (const float*)d_in[3];
    const float* W_base = (const float*)d_in[4];
    const float* b_base = (const float*)d_in[5];
    float* out = (float*)d_out;

    cudaFuncSetAttribute(gemm_lora, cudaFuncAttributeMaxDynamicSharedMemorySize, LORA_SMEM);

    pack_xh<<<(N_TOK * D_MODEL / 4 + 255) / 256, 256>>>(x);
    pack_wh<<<(NCAT2 * D_MODEL + 255) / 256, 256>>>(A, W_base);
    pack_bt<<<(D_MODEL * H_COLS + 255) / 256, 256>>>(Bmat);

    gate_kernel<<<N_TOK / 32, 256>>>(x, W_gate);          // 256 blocks, 4 tok/warp

    dim3 gridA(9, N_TOK / 128);                           // (9, 64)
    gemm_main<<<gridA, 256>>>(b_base, out);

    dim3 gridC(D_MODEL / 128, N_TOK / 128);               // (8, 64)
    gemm_lora<<<gridC, 256, LORA_SMEM>>>(out);
}

// round 7
// speedup vs baseline: 5.9669x; 1.0970x over previous
#include <cuda_runtime.h>
#include <cuda_fp16.h>
#include <cstdint>
#include <math.h>

#define N_TOK   8192
#define D_MODEL 1024
#define N_EXP   8
#define RANK    16
#define H_COLS  128
#define NCAT2   (D_MODEL + H_COLS)   // 1152 = 9 * 128

// ---------------- device scratch (no-alloc rule) ----------------
__device__ __align__(16) __half g_xh[N_TOK * D_MODEL];      // x as fp16
__device__ __align__(16) __half g_wh[NCAT2 * D_MODEL];      // [Wbase^T | A] fp16, [j][k]
__device__ __align__(16) __half g_bthi[D_MODEL * H_COLS];   // B^T hi fp16 [d][r]
__device__ __align__(16) __half g_btlo[D_MODEL * H_COLS];   // B^T lo fp16 [d][r]
__device__ __align__(16) float  g_h[N_TOK * H_COLS];        // lora hidden, fp32
__device__ __align__(16) float  g_c[N_TOK * N_EXP];         // dense combine weights

// ---------------- small asm helpers (all legal at compute_103) ----------------
__device__ __forceinline__ uint32_t smem_u32(const void* p) {
    uint32_t a;
    asm("{ .reg .u64 t; cvta.to.shared.u64 t, %1; cvt.u32.u64 %0, t; }" : "=r"(a) : "l"(p));
    return a;
}
__device__ __forceinline__ void cp16(uint32_t s, const void* g) {
    asm volatile("cp.async.cg.shared.global [%0], [%1], 16;" :: "r"(s), "l"(g));
}
__device__ __forceinline__ void cp_commit() {
    asm volatile("cp.async.commit_group;" ::: "memory");
}
template<int N> __device__ __forceinline__ void cp_wait() {
    asm volatile("cp.async.wait_group %0;" :: "n"(N) : "memory");
}
__device__ __forceinline__ void ldm4(uint32_t (&r)[4], uint32_t a) {
    asm volatile("ldmatrix.sync.aligned.m8n8.x4.shared.b16 {%0,%1,%2,%3}, [%4];"
        : "=r"(r[0]), "=r"(r[1]), "=r"(r[2]), "=r"(r[3]) : "r"(a));
}
__device__ __forceinline__ void mma16816(float* c, const uint32_t* a, const uint32_t* b) {
    asm volatile("mma.sync.aligned.m16n8k16.row.col.f32.f16.f16.f32 "
        "{%0,%1,%2,%3}, {%4,%5,%6,%7}, {%8,%9}, {%0,%1,%2,%3};"
        : "+f"(c[0]), "+f"(c[1]), "+f"(c[2]), "+f"(c[3])
        : "r"(a[0]), "r"(a[1]), "r"(a[2]), "r"(a[3]), "r"(b[0]), "r"(b[1]));
}
__device__ __forceinline__ uint32_t h2u(__half2 h) { return *reinterpret_cast<uint32_t*>(&h); }

// ---------------------------------------------------------------------------
// Fused pack x -> fp16 + fp32 gate (top-2 softmax -> dense combine weights)
// One block = 32 tokens (8 warps x 4 tokens). W_gate staged in smem (32KB).
// x read ONCE (float4), fp16 copy written, logits accumulated in fp32.
// ---------------------------------------------------------------------------
__global__ __launch_bounds__(256)
void pack_gate(const float* __restrict__ x, const float* __restrict__ Wg) {
    __shared__ float sWg[N_EXP][D_MODEL];          // 32 KB
    const int tid = threadIdx.x, l = tid & 31, wid = tid >> 5;

    // stage W_gate: 8192 floats = 2048 float4
#pragma unroll
    for (int i = 0; i < 8; i++) {
        int f4 = tid + i * 256;                    // 0..2047
        reinterpret_cast<float4*>(&sWg[0][0])[f4] =
            reinterpret_cast<const float4*>(Wg)[f4];
    }
    __syncthreads();

    const int t0 = blockIdx.x * 32 + wid * 4;
    float acc[4][N_EXP];
#pragma unroll
    for (int t = 0; t < 4; t++)
#pragma unroll
        for (int e = 0; e < N_EXP; e++) acc[t][e] = 0.f;

#pragma unroll
    for (int i = 0; i < 8; i++) {
        const int k = i * 128 + l * 4;
        float4 wv[N_EXP];
#pragma unroll
        for (int e = 0; e < N_EXP; e++)
            wv[e] = *reinterpret_cast<const float4*>(&sWg[e][k]);
#pragma unroll
        for (int t = 0; t < 4; t++) {
            const size_t off = (size_t)(t0 + t) * D_MODEL + k;
            float4 xv = *reinterpret_cast<const float4*>(x + off);
            // fp16 copy (coalesced 8B/lane)
            uint2 u;
            u.x = h2u(__floats2half2_rn(xv.x, xv.y));
            u.y = h2u(__floats2half2_rn(xv.z, xv.w));
            *reinterpret_cast<uint2*>(g_xh + off) = u;
            // fp32 logit accumulation
#pragma unroll
            for (int e = 0; e < N_EXP; e++) {
                acc[t][e] = fmaf(xv.x, wv[e].x, acc[t][e]);
                acc[t][e] = fmaf(xv.y, wv[e].y, acc[t][e]);
                acc[t][e] = fmaf(xv.z, wv[e].z, acc[t][e]);
                acc[t][e] = fmaf(xv.w, wv[e].w, acc[t][e]);
            }
        }
    }

    // warp reduce all 32 accumulators
#pragma unroll
    for (int o = 16; o; o >>= 1)
#pragma unroll
        for (int t = 0; t < 4; t++)
#pragma unroll
            for (int e = 0; e < N_EXP; e++)
                acc[t][e] += __shfl_xor_sync(0xffffffffu, acc[t][e], o);

    if (l == 0) {
#pragma unroll
        for (int t = 0; t < 4; t++) {
            float* lg = acc[t];
            int i0 = 0; float v0 = lg[0];
#pragma unroll
            for (int e = 1; e < N_EXP; e++) if (lg[e] > v0) { v0 = lg[e]; i0 = e; }
            int i1 = -1; float v1 = -1e30f;
#pragma unroll
            for (int e = 0; e < N_EXP; e++) if (e != i0 && lg[e] > v1) { v1 = lg[e]; i1 = e; }
            float e1 = expf(v1 - v0);
            float inv = 1.0f / (1.0f + e1);
#pragma unroll
            for (int e = 0; e < N_EXP; e++)
                g_c[(size_t)(t0 + t) * N_EXP + e] = (e == i0) ? inv : (e == i1) ? e1 * inv : 0.f;
        }
    }
}

// ---------------------------------------------------------------------------
// Pack kernels (weights)
// ---------------------------------------------------------------------------
__global__ void pack_wh(const float* __restrict__ A, const float* __restrict__ Wb) {
    int idx = blockIdx.x * blockDim.x + threadIdx.x;
    if (idx >= NCAT2 * D_MODEL) return;
    int j = idx >> 10, k = idx & 1023;
    float v;
    if (j < D_MODEL) v = Wb[j * D_MODEL + k];
    else {
        int jj = j - D_MODEL;
        v = A[((size_t)((jj >> 4) * D_MODEL) + k) * RANK + (jj & 15)];
    }
    g_wh[idx] = __float2half_rn(v);
}

__global__ void pack_bt(const float* __restrict__ Bmat) {
    int idx = blockIdx.x * blockDim.x + threadIdx.x;
    if (idx >= D_MODEL * H_COLS) return;
    int d = idx >> 7, r = idx & 127;
    float v = Bmat[(size_t)r * D_MODEL + d];
    __half h = __float2half_rn(v);
    g_bthi[idx] = h;
    g_btlo[idx] = __float2half_rn(v - __half2float(h));
}

// ---------------------------------------------------------------------------
// Main GEMM: C[8192, 1152] = x_h @ Wcat_h^T  (fp16 mma.sync, 1 pass)
// CTA 128x128, BK=32 halves, 8 warps (2M x 4N), cp.async double buffer.
// Epilogue: bx<8 -> out + bias ; bx==8 -> g_h (fp32)
// Swizzle for 64B rows: chunk' = c ^ ((r>>1)&3)
// ---------------------------------------------------------------------------
#define SWA(r, c) ((uint32_t)((r) * 64 + (((c) ^ (((r) >> 1) & 3)) << 4)))

__global__ __launch_bounds__(256, 2)
void gemm_main(const float* __restrict__ b_base, float* __restrict__ out) {
    __shared__ __align__(16) __half sA[2][128 * 32];
    __shared__ __align__(16) __half sB[2][128 * 32];
    const int tid = threadIdx.x, l = tid & 31, wid = tid >> 5;
    const int wm = wid >> 2, wn = wid & 3;
    const int m0 = blockIdx.y * 128, n0 = blockIdx.x * 128;
    const uint32_t sa0 = smem_u32(sA), sb0 = smem_u32(sB);

    float acc[4][4][4];
#pragma unroll
    for (int i = 0; i < 4; i++)
#pragma unroll
        for (int j = 0; j < 4; j++)
#pragma unroll
            for (int k = 0; k < 4; k++) acc[i][j][k] = 0.f;

    auto load_tile = [&](int st, int kt) {
#pragma unroll
        for (int p = 0; p < 2; p++) {
            int cid = tid + p * 256;          // 0..511
            int r = cid >> 2, c = cid & 3;
            uint32_t sw = SWA(r, c);
            cp16(sa0 + st * 8192 + sw, g_xh + (size_t)(m0 + r) * D_MODEL + kt + c * 8);
            cp16(sb0 + st * 8192 + sw, g_wh + (size_t)(n0 + r) * D_MODEL + kt + c * 8);
        }
    };

    load_tile(0, 0);
    cp_commit();

    const int NIT = D_MODEL / 32;
    for (int it = 0; it < NIT; it++) {
        const int st = it & 1;
        if (it + 1 < NIT) { load_tile(st ^ 1, (it + 1) * 32); cp_commit(); cp_wait<1>(); }
        else              { cp_wait<0>(); }
        __syncthreads();

        const uint32_t aBase = sa0 + st * 8192;
        const uint32_t bBase = sb0 + st * 8192;
#pragma unroll
        for (int ks = 0; ks < 2; ks++) {
            uint32_t af[4][4];
#pragma unroll
            for (int mt = 0; mt < 4; mt++) {
                int row = wm * 64 + mt * 16 + (l & 15);
                int ch = ks * 2 + (l >> 4);
                ldm4(af[mt], aBase + SWA(row, ch));
            }
#pragma unroll
            for (int q = 0; q < 2; q++) {
                uint32_t bf[4];
                int rn = wn * 32 + q * 16 + ((l >> 4) << 3) + (l & 7);
                int ch = ks * 2 + ((l >> 3) & 1);
                ldm4(bf, bBase + SWA(rn, ch));
#pragma unroll
                for (int mt = 0; mt < 4; mt++) {
                    mma16816(acc[mt][q * 2],     af[mt], bf);
                    mma16816(acc[mt][q * 2 + 1], af[mt], bf + 2);
                }
            }
        }
        __syncthreads();
    }

    const bool isH = (blockIdx.x == 8);
#pragma unroll
    for (int mt = 0; mt < 4; mt++) {
        int r0 = m0 + wm * 64 + mt * 16 + (l >> 2);
#pragma unroll
        for (int nt = 0; nt < 4; nt++) {
            int j = n0 + wn * 32 + nt * 8 + (l & 3) * 2;
            float* a4 = acc[mt][nt];
            if (!isH) {
                float2 bb = *reinterpret_cast<const float2*>(b_base + j);
                float2 v0 = make_float2(a4[0] + bb.x, a4[1] + bb.y);
                float2 v1 = make_float2(a4[2] + bb.x, a4[3] + bb.y);
                *reinterpret_cast<float2*>(out + (size_t)r0 * D_MODEL + j) = v0;
                *reinterpret_cast<float2*>(out + (size_t)(r0 + 8) * D_MODEL + j) = v1;
            } else {
                int jc = j - D_MODEL;
                *reinterpret_cast<float2*>(g_h + (size_t)r0 * H_COLS + jc) =
                    make_float2(a4[0], a4[1]);
                *reinterpret_cast<float2*>(g_h + (size_t)(r0 + 8) * H_COLS + jc) =
                    make_float2(a4[2], a4[3]);
            }
        }
    }
}

// ---------------------------------------------------------------------------
// LoRA up-proj: out += (c * h)[8192,128] @ B[128,1024]
// fp16 3-pass hi/lo split (hh + hi*lo + lo*hi). K=128 single shot.
// 256B rows: chunk' = c ^ (r&7). SMEM: Ahi|Alo|Bhi|Blo = 4 x 32KB.
// ---------------------------------------------------------------------------
#define SWL(r, c) ((uint32_t)((r) * 256 + (((c) ^ ((r) & 7)) << 4)))
#define LSM_AHI 0
#define LSM_ALO 32768
#define LSM_BHI 65536
#define LSM_BLO 98304
#define LORA_SMEM 131072

__global__ __launch_bounds__(256, 1)
void gemm_lora(float* __restrict__ out) {
    extern __shared__ __align__(16) char ls[];
    const uint32_t sb = smem_u32(ls);
    const int tid = threadIdx.x, l = tid & 31, wid = tid >> 5;
    const int wm = wid >> 2, wn = wid & 3;
    const int m0 = blockIdx.y * 128, n0 = blockIdx.x * 128;

    // B tiles (pre-split fp16) via cp.async
#pragma unroll
    for (int i = 0; i < 8; i++) {
        int cid = tid + i * 256;            // 0..2047: r(128) x ch(16)
        int r = cid >> 4, ch = cid & 15;
        uint32_t sw = SWL(r, ch);
        cp16(sb + LSM_BHI + sw, g_bthi + (size_t)(n0 + r) * H_COLS + ch * 8);
        cp16(sb + LSM_BLO + sw, g_btlo + (size_t)(n0 + r) * H_COLS + ch * 8);
    }
    cp_commit();

    // A tiles: read h (fp32), scale by combine weight, split hi/lo
#pragma unroll
    for (int i = 0; i < 16; i++) {
        int fid = tid + i * 256;            // 0..4095: r(128) x c4(32)
        int r = fid >> 5, c4 = fid & 31;
        int m = m0 + r;
        float s = g_c[(size_t)m * N_EXP + (c4 >> 2)];
        float4 v = *reinterpret_cast<const float4*>(g_h + (size_t)m * H_COLS + c4 * 4);
        v.x *= s; v.y *= s; v.z *= s; v.w *= s;
        __half2 hA = __floats2half2_rn(v.x, v.y);
        __half2 hB = __floats2half2_rn(v.z, v.w);
        __half2 lA = __floats2half2_rn(v.x - __low2float(hA), v.y - __high2float(hA));
        __half2 lB = __floats2half2_rn(v.z - __low2float(hB), v.w - __high2float(hB));
        uint32_t off = SWL(r, c4 >> 1) + (c4 & 1) * 8;
        *reinterpret_cast<uint2*>(ls + LSM_AHI + off) = make_uint2(h2u(hA), h2u(hB));
        *reinterpret_cast<uint2*>(ls + LSM_ALO + off) = make_uint2(h2u(lA), h2u(lB));
    }
    cp_wait<0>();
    __syncthreads();

    float acc[4][4][4];
#pragma unroll
    for (int i = 0; i < 4; i++)
#pragma unroll
        for (int j = 0; j < 4; j++)
#pragma unroll
            for (int k = 0; k < 4; k++) acc[i][j][k] = 0.f;

#pragma unroll
    for (int pass = 0; pass < 3; pass++) {
        const uint32_t aBase = sb + (pass == 2 ? LSM_ALO : LSM_AHI);
        const uint32_t bBase = sb + (pass == 1 ? LSM_BLO : LSM_BHI);
#pragma unroll
        for (int ks = 0; ks < 8; ks++) {
            uint32_t af[4][4];
#pragma unroll
            for (int mt = 0; mt < 4; mt++) {
                int row = wm * 64 + mt * 16 + (l & 15);
                int ch = ks * 2 + (l >> 4);
                ldm4(af[mt], aBase + SWL(row, ch));
            }
#pragma unroll
            for (int q = 0; q < 2; q++) {
                uint32_t bf[4];
                int rn = wn * 32 + q * 16 + ((l >> 4) << 3) + (l & 7);
                int ch = ks * 2 + ((l >> 3) & 1);
                ldm4(bf, bBase + SWL(rn, ch));
#pragma unroll
                for (int mt = 0; mt < 4; mt++) {
                    mma16816(acc[mt][q * 2],     af[mt], bf);
                    mma16816(acc[mt][q * 2 + 1], af[mt], bf + 2);
                }
            }
        }
    }

    // epilogue: read-modify-write out
#pragma unroll
    for (int mt = 0; mt < 4; mt++) {
        int r0 = m0 + wm * 64 + mt * 16 + (l >> 2);
#pragma unroll
        for (int nt = 0; nt < 4; nt++) {
            int j = n0 + wn * 32 + nt * 8 + (l & 3) * 2;
            float* a4 = acc[mt][nt];
            float2* p0 = reinterpret_cast<float2*>(out + (size_t)r0 * D_MODEL + j);
            float2* p1 = reinterpret_cast<float2*>(out + (size_t)(r0 + 8) * D_MODEL + j);
            float2 o0 = *p0, o1 = *p1;
            o0.x += a4[0]; o0.y += a4[1];
            o1.x += a4[2]; o1.y += a4[3];
            *p0 = o0; *p1 = o1;
        }
    }
}

// ---------------------------------------------------------------------------
extern "C" void kernel_launch(void* const* d_in, const int* in_sizes, int n_in,
                              void* d_out, int out_size) {
    const float* x      = (const float*)d_in[0];
    const float* W_gate = (const float*)d_in[1];
    const float* A      = (const float*)d_in[2];
    const float* Bmat   = (const float*)d_in[3];
    const float* W_base = (const float*)d_in[4];
    const float* b_base = (const float*)d_in[5];
    float* out = (float*)d_out;

    cudaFuncSetAttribute(gemm_lora, cudaFuncAttributeMaxDynamicSharedMemorySize, LORA_SMEM);

    pack_gate<<<N_TOK / 32, 256>>>(x, W_gate);            // fused x->fp16 + gating
    pack_wh<<<(NCAT2 * D_MODEL + 255) / 256, 256>>>(A, W_base);
    pack_bt<<<(D_MODEL * H_COLS + 255) / 256, 256>>>(Bmat);

    dim3 gridA(9, N_TOK / 128);                           // (9, 64)
    gemm_main<<<gridA, 256>>>(b_base, out);

    dim3 gridC(D_MODEL / 128, N_TOK / 128);               // (8, 64)
    gemm_lora<<<gridC, 256, LORA_SMEM>>>(out);
}

// round 8
// speedup vs baseline: 6.7514x; 1.1315x over previous
#include <cuda_runtime.h>
#include <cuda_fp16.h>
#include <cstdint>
#include <math.h>

#define N_TOK   8192
#define D_MODEL 1024
#define N_EXP   8
#define RANK    16
#define H_COLS  128
#define K2      (D_MODEL + H_COLS)   // 1152 concatenated K

// ---------------- device scratch (no-alloc rule) ----------------
__device__ __align__(16) __half g_xe[N_TOK * K2];        // [x | c*h] fp16, row-major stride 1152
__device__ __align__(16) __half g_w2[D_MODEL * K2];      // [Wbase^T ; B] fp16: row d, col k
__device__ __align__(16) __half g_at[H_COLS * D_MODEL];  // A^T fp16: [er][d]
__device__ __align__(16) float  g_c[N_TOK * N_EXP];      // dense combine weights

// ---------------- asm helpers (legal at compute_103) ----------------
__device__ __forceinline__ uint32_t smem_u32(const void* p) {
    uint32_t a;
    asm("{ .reg .u64 t; cvta.to.shared.u64 t, %1; cvt.u32.u64 %0, t; }" : "=r"(a) : "l"(p));
    return a;
}
__device__ __forceinline__ void cp16(uint32_t s, const void* g) {
    asm volatile("cp.async.cg.shared.global [%0], [%1], 16;" :: "r"(s), "l"(g));
}
__device__ __forceinline__ void cp_commit() {
    asm volatile("cp.async.commit_group;" ::: "memory");
}
template<int N> __device__ __forceinline__ void cp_wait() {
    asm volatile("cp.async.wait_group %0;" :: "n"(N) : "memory");
}
__device__ __forceinline__ void ldm4(uint32_t (&r)[4], uint32_t a) {
    asm volatile("ldmatrix.sync.aligned.m8n8.x4.shared.b16 {%0,%1,%2,%3}, [%4];"
        : "=r"(r[0]), "=r"(r[1]), "=r"(r[2]), "=r"(r[3]) : "r"(a));
}
__device__ __forceinline__ void mma16816(float* c, const uint32_t* a, const uint32_t* b) {
    asm volatile("mma.sync.aligned.m16n8k16.row.col.f32.f16.f16.f32 "
        "{%0,%1,%2,%3}, {%4,%5,%6,%7}, {%8,%9}, {%0,%1,%2,%3};"
        : "+f"(c[0]), "+f"(c[1]), "+f"(c[2]), "+f"(c[3])
        : "r"(a[0]), "r"(a[1]), "r"(a[2]), "r"(a[3]), "r"(b[0]), "r"(b[1]));
}
__device__ __forceinline__ uint32_t h2u(__half2 h) { return *reinterpret_cast<uint32_t*>(&h); }

// smem swizzle for 64B rows (32 halves): chunk' = c ^ ((r>>1)&3)
#define SWA(r, c) ((uint32_t)((r) * 64 + (((c) ^ (((r) >> 1) & 3)) << 4)))

// ---------------------------------------------------------------------------
// Fused pack x -> fp16 (into xe[:,0:1024]) + fp32 gate -> dense combine g_c
// ---------------------------------------------------------------------------
__global__ __launch_bounds__(256)
void pack_gate(const float* __restrict__ x, const float* __restrict__ Wg) {
    __shared__ float sWg[N_EXP][D_MODEL];          // 32 KB
    const int tid = threadIdx.x, l = tid & 31, wid = tid >> 5;

#pragma unroll
    for (int i = 0; i < 8; i++) {
        int f4 = tid + i * 256;
        reinterpret_cast<float4*>(&sWg[0][0])[f4] =
            reinterpret_cast<const float4*>(Wg)[f4];
    }
    __syncthreads();

    const int t0 = blockIdx.x * 32 + wid * 4;
    float acc[4][N_EXP];
#pragma unroll
    for (int t = 0; t < 4; t++)
#pragma unroll
        for (int e = 0; e < N_EXP; e++) acc[t][e] = 0.f;

#pragma unroll
    for (int i = 0; i < 8; i++) {
        const int k = i * 128 + l * 4;
        float4 wv[N_EXP];
#pragma unroll
        for (int e = 0; e < N_EXP; e++)
            wv[e] = *reinterpret_cast<const float4*>(&sWg[e][k]);
#pragma unroll
        for (int t = 0; t < 4; t++) {
            float4 xv = *reinterpret_cast<const float4*>(x + (size_t)(t0 + t) * D_MODEL + k);
            uint2 u;
            u.x = h2u(__floats2half2_rn(xv.x, xv.y));
            u.y = h2u(__floats2half2_rn(xv.z, xv.w));
            *reinterpret_cast<uint2*>(g_xe + (size_t)(t0 + t) * K2 + k) = u;
#pragma unroll
            for (int e = 0; e < N_EXP; e++) {
                acc[t][e] = fmaf(xv.x, wv[e].x, acc[t][e]);
                acc[t][e] = fmaf(xv.y, wv[e].y, acc[t][e]);
                acc[t][e] = fmaf(xv.z, wv[e].z, acc[t][e]);
                acc[t][e] = fmaf(xv.w, wv[e].w, acc[t][e]);
            }
        }
    }

#pragma unroll
    for (int o = 16; o; o >>= 1)
#pragma unroll
        for (int t = 0; t < 4; t++)
#pragma unroll
            for (int e = 0; e < N_EXP; e++)
                acc[t][e] += __shfl_xor_sync(0xffffffffu, acc[t][e], o);

    if (l == 0) {
#pragma unroll
        for (int t = 0; t < 4; t++) {
            float* lg = acc[t];
            int i0 = 0; float v0 = lg[0];
#pragma unroll
            for (int e = 1; e < N_EXP; e++) if (lg[e] > v0) { v0 = lg[e]; i0 = e; }
            int i1 = -1; float v1 = -1e30f;
#pragma unroll
            for (int e = 0; e < N_EXP; e++) if (e != i0 && lg[e] > v1) { v1 = lg[e]; i1 = e; }
            float e1 = expf(v1 - v0);
            float inv = 1.0f / (1.0f + e1);
#pragma unroll
            for (int e = 0; e < N_EXP; e++)
                g_c[(size_t)(t0 + t) * N_EXP + e] = (e == i0) ? inv : (e == i1) ? e1 * inv : 0.f;
        }
    }
}

// ---------------------------------------------------------------------------
// Weight packs
// ---------------------------------------------------------------------------
__global__ void pack_w2(const float* __restrict__ Wb, const float* __restrict__ Bmat) {
    int idx = blockIdx.x * blockDim.x + threadIdx.x;
    if (idx >= D_MODEL * K2) return;
    int d = idx / K2, k = idx - d * K2;
    float v = (k < D_MODEL) ? Wb[(size_t)d * D_MODEL + k]
                            : Bmat[(size_t)(k - D_MODEL) * D_MODEL + d];
    g_w2[idx] = __float2half_rn(v);
}

__global__ void pack_at(const float* __restrict__ A) {
    int idx = blockIdx.x * blockDim.x + threadIdx.x;
    if (idx >= H_COLS * D_MODEL) return;
    int er = idx >> 10, d = idx & 1023;
    int e = er >> 4, r = er & 15;
    g_at[idx] = __float2half_rn(A[((size_t)e * D_MODEL + d) * RANK + r]);
}

// ---------------------------------------------------------------------------
// gemm_h: h[8192,128] = xe[:, :1024] @ A^T ; epilogue: *combine -> fp16 -> xe[:,1024:]
// CTA 64x128, BK=32, double buffer, 8 warps (2M x 4N), warp tile 32x32.
// ---------------------------------------------------------------------------
__global__ __launch_bounds__(256, 2)
void gemm_h() {
    __shared__ __align__(16) __half sA[2][64 * 32];
    __shared__ __align__(16) __half sB[2][128 * 32];
    const int tid = threadIdx.x, l = tid & 31, wid = tid >> 5;
    const int wm = wid >> 2, wn = wid & 3;
    const int m0 = blockIdx.y * 64;
    const uint32_t sa0 = smem_u32(sA), sb0 = smem_u32(sB);

    float acc[2][4][4];
#pragma unroll
    for (int i = 0; i < 2; i++)
#pragma unroll
        for (int j = 0; j < 4; j++)
#pragma unroll
            for (int k = 0; k < 4; k++) acc[i][j][k] = 0.f;

    auto load_tile = [&](int st, int kt) {
        {   // A: 64 rows x 4 chunks = 256 cp16
            int r = tid >> 2, c = tid & 3;
            cp16(sa0 + st * 4096 + SWA(r, c), g_xe + (size_t)(m0 + r) * K2 + kt + c * 8);
        }
#pragma unroll
        for (int p = 0; p < 2; p++) {   // B: 128 rows x 4 chunks = 512 cp16
            int cid = tid + p * 256;
            int r = cid >> 2, c = cid & 3;
            cp16(sb0 + st * 8192 + SWA(r, c), g_at + (size_t)r * D_MODEL + kt + c * 8);
        }
    };

    load_tile(0, 0);
    cp_commit();

    const int NIT = D_MODEL / 32;
    for (int it = 0; it < NIT; it++) {
        const int st = it & 1;
        if (it + 1 < NIT) { load_tile(st ^ 1, (it + 1) * 32); cp_commit(); cp_wait<1>(); }
        else              { cp_wait<0>(); }
        __syncthreads();

        const uint32_t aBase = sa0 + st * 4096;
        const uint32_t bBase = sb0 + st * 8192;
#pragma unroll
        for (int ks = 0; ks < 2; ks++) {
            uint32_t af[2][4];
#pragma unroll
            for (int mt = 0; mt < 2; mt++) {
                int row = wm * 32 + mt * 16 + (l & 15);
                int ch = ks * 2 + (l >> 4);
                ldm4(af[mt], aBase + SWA(row, ch));
            }
#pragma unroll
            for (int q = 0; q < 2; q++) {
                uint32_t bf[4];
                int rn = wn * 32 + q * 16 + ((l >> 4) << 3) + (l & 7);
                int ch = ks * 2 + ((l >> 3) & 1);
                ldm4(bf, bBase + SWA(rn, ch));
#pragma unroll
                for (int mt = 0; mt < 2; mt++) {
                    mma16816(acc[mt][q * 2],     af[mt], bf);
                    mma16816(acc[mt][q * 2 + 1], af[mt], bf + 2);
                }
            }
        }
        __syncthreads();
    }

    // epilogue: scale by combine weight, fp16, store into xe[:, 1024+j]
#pragma unroll
    for (int mt = 0; mt < 2; mt++) {
        int r0 = m0 + wm * 32 + mt * 16 + (l >> 2);
#pragma unroll
        for (int nt = 0; nt < 4; nt++) {
            int j = wn * 32 + nt * 8 + (l & 3) * 2;
            int e = j >> 4;
            float* a4 = acc[mt][nt];
            float s0 = g_c[(size_t)r0 * N_EXP + e];
            float s1 = g_c[(size_t)(r0 + 8) * N_EXP + e];
            __half2 h0 = __floats2half2_rn(a4[0] * s0, a4[1] * s0);
            __half2 h1 = __floats2half2_rn(a4[2] * s1, a4[3] * s1);
            *reinterpret_cast<uint32_t*>(g_xe + (size_t)r0 * K2 + D_MODEL + j) = h2u(h0);
            *reinterpret_cast<uint32_t*>(g_xe + (size_t)(r0 + 8) * K2 + D_MODEL + j) = h2u(h1);
        }
    }
}

// ---------------------------------------------------------------------------
// gemm_main: out[8192,1024] = xe[8192,1152] @ W2^T + bias  (write-only epilogue)
// CTA 256x128, BK=32, 3-stage cp.async, 8 warps (4M x 2N), warp tile 64x64.
// ---------------------------------------------------------------------------
#define MST_A   16384u                 // A bytes per stage (256*32*2)
#define MST_B   8192u                  // B bytes per stage
#define MST     (MST_A + MST_B)        // 24576 per stage
#define MAIN_SMEM (3 * MST)            // 73728

__global__ __launch_bounds__(256, 1)
void gemm_main(const float* __restrict__ b_base, float* __restrict__ out) {
    extern __shared__ __align__(16) char ms[];
    const uint32_t s0 = smem_u32(ms);
    const int tid = threadIdx.x, l = tid & 31, wid = tid >> 5;
    const int wm = wid >> 1, wn = wid & 1;
    const int m0 = blockIdx.y * 256, n0 = blockIdx.x * 128;

    float acc[4][8][4];
#pragma unroll
    for (int i = 0; i < 4; i++)
#pragma unroll
        for (int j = 0; j < 8; j++)
#pragma unroll
            for (int k = 0; k < 4; k++) acc[i][j][k] = 0.f;

    auto load_tile = [&](int st, int kt) {
        const uint32_t base = s0 + st * MST;
#pragma unroll
        for (int p = 0; p < 4; p++) {   // A: 256 rows x 4 chunks = 1024 cp16
            int cid = tid + p * 256;
            int r = cid >> 2, c = cid & 3;
            cp16(base + SWA(r, c), g_xe + (size_t)(m0 + r) * K2 + kt + c * 8);
        }
#pragma unroll
        for (int p = 0; p < 2; p++) {   // B: 128 rows x 4 chunks = 512 cp16
            int cid = tid + p * 256;
            int r = cid >> 2, c = cid & 3;
            cp16(base + MST_A + SWA(r, c), g_w2 + (size_t)(n0 + r) * K2 + kt + c * 8);
        }
    };

    load_tile(0, 0); cp_commit();
    load_tile(1, 32); cp_commit();

    const int NIT = K2 / 32;            // 36
    for (int it = 0; it < NIT; it++) {
        const int st = it % 3;
        if (it == NIT - 1) cp_wait<0>(); else cp_wait<1>();
        __syncthreads();

        if (it + 2 < NIT) { load_tile((it + 2) % 3, (it + 2) * 32); cp_commit(); }

        const uint32_t aBase = s0 + st * MST;
        const uint32_t bBase = aBase + MST_A;
#pragma unroll
        for (int ks = 0; ks < 2; ks++) {
            uint32_t af[4][4];
#pragma unroll
            for (int mt = 0; mt < 4; mt++) {
                int row = wm * 64 + mt * 16 + (l & 15);
                int ch = ks * 2 + (l >> 4);
                ldm4(af[mt], aBase + SWA(row, ch));
            }
#pragma unroll
            for (int q = 0; q < 4; q++) {
                uint32_t bf[4];
                int rn = wn * 64 + q * 16 + ((l >> 4) << 3) + (l & 7);
                int ch = ks * 2 + ((l >> 3) & 1);
                ldm4(bf, bBase + SWA(rn, ch));
#pragma unroll
                for (int mt = 0; mt < 4; mt++) {
                    mma16816(acc[mt][q * 2],     af[mt], bf);
                    mma16816(acc[mt][q * 2 + 1], af[mt], bf + 2);
                }
            }
        }
        __syncthreads();
    }

    // epilogue: + bias, write out (no RMW)
#pragma unroll
    for (int mt = 0; mt < 4; mt++) {
        int r0 = m0 + wm * 64 + mt * 16 + (l >> 2);
#pragma unroll
        for (int nt = 0; nt < 8; nt++) {
            int j = n0 + wn * 64 + nt * 8 + (l & 3) * 2;
            float* a4 = acc[mt][nt];
            float2 bb = *reinterpret_cast<const float2*>(b_base + j);
            *reinterpret_cast<float2*>(out + (size_t)r0 * D_MODEL + j) =
                make_float2(a4[0] + bb.x, a4[1] + bb.y);
            *reinterpret_cast<float2*>(out + (size_t)(r0 + 8) * D_MODEL + j) =
                make_float2(a4[2] + bb.x, a4[3] + bb.y);
        }
    }
}

// ---------------------------------------------------------------------------
extern "C" void kernel_launch(void* const* d_in, const int* in_sizes, int n_in,
                              void* d_out, int out_size) {
    const float* x      = (const float*)d_in[0];
    const float* W_gate = (const float*)d_in[1];
    const float* A      = (const float*)d_in[2];
    const float* Bmat   = (const float*)d_in[3];
    const float* W_base = (const float*)d_in[4];
    const float* b_base = (const float*)d_in[5];
    float* out = (float*)d_out;

    cudaFuncSetAttribute(gemm_main, cudaFuncAttributeMaxDynamicSharedMemorySize, MAIN_SMEM);

    pack_gate<<<N_TOK / 32, 256>>>(x, W_gate);
    pack_w2<<<(D_MODEL * K2 + 255) / 256, 256>>>(W_base, Bmat);
    pack_at<<<(H_COLS * D_MODEL + 255) / 256, 256>>>(A);

    gemm_h<<<dim3(1, N_TOK / 64), 256>>>();

    gemm_main<<<dim3(D_MODEL / 128, N_TOK / 256), 256, MAIN_SMEM>>>(b_base, out);
}

// round 10
// speedup vs baseline: 8.0028x; 1.1854x over previous
#include <cuda_runtime.h>
#include <cuda_fp16.h>
#include <cstdint>
#include <math.h>

#define N_TOK   8192
#define D_MODEL 1024
#define N_EXP   8
#define RANK    16
#define H_COLS  128
#define K2      (D_MODEL + H_COLS)   // 1152 concatenated K

// ---------------- device scratch (no-alloc rule) ----------------
__device__ __align__(16) __half g_xe[N_TOK * K2];        // [x | c*h] fp16, row stride 1152
__device__ __align__(16) __half g_w2[D_MODEL * K2];      // [Wbase^T ; B] fp16: row d, col k
__device__ __align__(16) __half g_at[H_COLS * D_MODEL];  // A^T fp16: [er][d]
__device__ __align__(16) float  g_c[N_TOK * N_EXP];      // dense combine weights

// ---------------- asm helpers (legal at compute_103) ----------------
__device__ __forceinline__ uint32_t smem_u32(const void* p) {
    uint32_t a;
    asm("{ .reg .u64 t; cvta.to.shared.u64 t, %1; cvt.u32.u64 %0, t; }" : "=r"(a) : "l"(p));
    return a;
}
__device__ __forceinline__ void cp16(uint32_t s, const void* g) {
    asm volatile("cp.async.cg.shared.global [%0], [%1], 16;" :: "r"(s), "l"(g));
}
__device__ __forceinline__ void cp_commit() {
    asm volatile("cp.async.commit_group;" ::: "memory");
}
template<int N> __device__ __forceinline__ void cp_wait() {
    asm volatile("cp.async.wait_group %0;" :: "n"(N) : "memory");
}
__device__ __forceinline__ void ldm4(uint32_t (&r)[4], uint32_t a) {
    asm volatile("ldmatrix.sync.aligned.m8n8.x4.shared.b16 {%0,%1,%2,%3}, [%4];"
        : "=r"(r[0]), "=r"(r[1]), "=r"(r[2]), "=r"(r[3]) : "r"(a));
}
__device__ __forceinline__ void mma16816(float* c, const uint32_t* a, const uint32_t* b) {
    asm volatile("mma.sync.aligned.m16n8k16.row.col.f32.f16.f16.f32 "
        "{%0,%1,%2,%3}, {%4,%5,%6,%7}, {%8,%9}, {%0,%1,%2,%3};"
        : "+f"(c[0]), "+f"(c[1]), "+f"(c[2]), "+f"(c[3])
        : "r"(a[0]), "r"(a[1]), "r"(a[2]), "r"(a[3]), "r"(b[0]), "r"(b[1]));
}
__device__ __forceinline__ uint32_t h2u(__half2 h) { return *reinterpret_cast<uint32_t*>(&h); }

// 128B-row swizzle (64 halves/row, 8 x 16B chunks): chunk' = c ^ (r&7)
#define SW64(r, c) ((uint32_t)((r) * 128 + (((c) ^ ((r) & 7)) << 4)))

// ---------------------------------------------------------------------------
// Fused pack x -> fp16 (into xe[:,0:1024]) + fp32 gate -> dense combine g_c
// ---------------------------------------------------------------------------
__global__ __launch_bounds__(256)
void pack_gate(const float* __restrict__ x, const float* __restrict__ Wg) {
    __shared__ float sWg[N_EXP][D_MODEL];          // 32 KB
    const int tid = threadIdx.x, l = tid & 31, wid = tid >> 5;

#pragma unroll
    for (int i = 0; i < 8; i++) {
        int f4 = tid + i * 256;
        reinterpret_cast<float4*>(&sWg[0][0])[f4] =
            reinterpret_cast<const float4*>(Wg)[f4];
    }
    __syncthreads();

    const int t0 = blockIdx.x * 32 + wid * 4;
    float acc[4][N_EXP];
#pragma unroll
    for (int t = 0; t < 4; t++)
#pragma unroll
        for (int e = 0; e < N_EXP; e++) acc[t][e] = 0.f;

#pragma unroll
    for (int i = 0; i < 8; i++) {
        const int k = i * 128 + l * 4;
        float4 wv[N_EXP];
#pragma unroll
        for (int e = 0; e < N_EXP; e++)
            wv[e] = *reinterpret_cast<const float4*>(&sWg[e][k]);
#pragma unroll
        for (int t = 0; t < 4; t++) {
            float4 xv = *reinterpret_cast<const float4*>(x + (size_t)(t0 + t) * D_MODEL + k);
            uint2 u;
            u.x = h2u(__floats2half2_rn(xv.x, xv.y));
            u.y = h2u(__floats2half2_rn(xv.z, xv.w));
            *reinterpret_cast<uint2*>(g_xe + (size_t)(t0 + t) * K2 + k) = u;
#pragma unroll
            for (int e = 0; e < N_EXP; e++) {
                acc[t][e] = fmaf(xv.x, wv[e].x, acc[t][e]);
                acc[t][e] = fmaf(xv.y, wv[e].y, acc[t][e]);
                acc[t][e] = fmaf(xv.z, wv[e].z, acc[t][e]);
                acc[t][e] = fmaf(xv.w, wv[e].w, acc[t][e]);
            }
        }
    }

#pragma unroll
    for (int o = 16; o; o >>= 1)
#pragma unroll
        for (int t = 0; t < 4; t++)
#pragma unroll
            for (int e = 0; e < N_EXP; e++)
                acc[t][e] += __shfl_xor_sync(0xffffffffu, acc[t][e], o);

    if (l == 0) {
#pragma unroll
        for (int t = 0; t < 4; t++) {
            float* lg = acc[t];
            int i0 = 0; float v0 = lg[0];
#pragma unroll
            for (int e = 1; e < N_EXP; e++) if (lg[e] > v0) { v0 = lg[e]; i0 = e; }
            int i1 = -1; float v1 = -1e30f;
#pragma unroll
            for (int e = 0; e < N_EXP; e++) if (e != i0 && lg[e] > v1) { v1 = lg[e]; i1 = e; }
            float e1 = expf(v1 - v0);
            float inv = 1.0f / (1.0f + e1);
#pragma unroll
            for (int e = 0; e < N_EXP; e++)
                g_c[(size_t)(t0 + t) * N_EXP + e] = (e == i0) ? inv : (e == i1) ? e1 * inv : 0.f;
        }
    }
}

// ---------------------------------------------------------------------------
// Weight packs
// ---------------------------------------------------------------------------
__global__ void pack_w2(const float* __restrict__ Wb, const float* __restrict__ Bmat) {
    int idx = blockIdx.x * blockDim.x + threadIdx.x;
    if (idx >= D_MODEL * K2) return;
    int d = idx / K2, k = idx - d * K2;
    float v = (k < D_MODEL) ? Wb[(size_t)d * D_MODEL + k]
                            : Bmat[(size_t)(k - D_MODEL) * D_MODEL + d];
    g_w2[idx] = __float2half_rn(v);
}

__global__ void pack_at(const float* __restrict__ A) {
    int idx = blockIdx.x * blockDim.x + threadIdx.x;
    if (idx >= H_COLS * D_MODEL) return;
    int er = idx >> 10, d = idx & 1023;
    int e = er >> 4, r = er & 15;
    g_at[idx] = __float2half_rn(A[((size_t)e * D_MODEL + d) * RANK + r]);
}

// ---------------------------------------------------------------------------
// gemm_h: h[8192,128] = xe[:, :1024] @ A^T ; epilogue *combine -> fp16 -> xe[:,1024:]
// CTA 32x128, 128 threads (4 warps, warp tile 32x32), BK=64, 3-stage. grid 256.
// ---------------------------------------------------------------------------
#define HST_A 4096u                   // 32*64*2
#define HST_B 16384u                  // 128*64*2
#define HST   (HST_A + HST_B)         // 20480
#define H_SMEM (3 * HST)              // 61440

__global__ __launch_bounds__(128, 3)
void gemm_h() {
    extern __shared__ __align__(16) char hs[];
    const uint32_t s0 = smem_u32(hs);
    const int tid = threadIdx.x, l = tid & 31, wn = tid >> 5;   // 4 warps: 1M x 4N
    const int m0 = blockIdx.x * 32;

    float acc[2][4][4];
#pragma unroll
    for (int i = 0; i < 2; i++)
#pragma unroll
        for (int j = 0; j < 4; j++)
#pragma unroll
            for (int k = 0; k < 4; k++) acc[i][j][k] = 0.f;

    auto load_tile = [&](int st, int kt) {
        const uint32_t base = s0 + st * HST;
#pragma unroll
        for (int p = 0; p < 2; p++) {   // A: 32 rows x 8 chunks = 256 cp16
            int cid = tid + p * 128;
            int r = cid >> 3, c = cid & 7;
            cp16(base + SW64(r, c), g_xe + (size_t)(m0 + r) * K2 + kt + c * 8);
        }
#pragma unroll
        for (int p = 0; p < 8; p++) {   // B: 128 rows x 8 chunks = 1024 cp16
            int cid = tid + p * 128;
            int r = cid >> 3, c = cid & 7;
            cp16(base + HST_A + SW64(r, c), g_at + (size_t)r * D_MODEL + kt + c * 8);
        }
    };

    load_tile(0, 0); cp_commit();
    load_tile(1, 64); cp_commit();

    const int NIT = D_MODEL / 64;       // 16
    for (int it = 0; it < NIT; it++) {
        const int st = it % 3;
        if (it == NIT - 1) cp_wait<0>(); else cp_wait<1>();
        __syncthreads();
        if (it + 2 < NIT) { load_tile((it + 2) % 3, (it + 2) * 64); cp_commit(); }

        const uint32_t aBase = s0 + st * HST;
        const uint32_t bBase = aBase + HST_A;
#pragma unroll
        for (int ks = 0; ks < 4; ks++) {
            uint32_t af[2][4];
#pragma unroll
            for (int mt = 0; mt < 2; mt++) {
                int row = mt * 16 + (l & 15);
                int ch = ks * 2 + (l >> 4);
                ldm4(af[mt], aBase + SW64(row, ch));
            }
#pragma unroll
            for (int q = 0; q < 2; q++) {
                uint32_t bf[4];
                int rn = wn * 32 + q * 16 + ((l >> 4) << 3) + (l & 7);
                int ch = ks * 2 + ((l >> 3) & 1);
                ldm4(bf, bBase + SW64(rn, ch));
#pragma unroll
                for (int mt = 0; mt < 2; mt++) {
                    mma16816(acc[mt][q * 2],     af[mt], bf);
                    mma16816(acc[mt][q * 2 + 1], af[mt], bf + 2);
                }
            }
        }
        __syncthreads();
    }

    // epilogue: scale by combine weight, fp16, store into xe[:, 1024+j]
#pragma unroll
    for (int mt = 0; mt < 2; mt++) {
        int r0 = m0 + mt * 16 + (l >> 2);
#pragma unroll
        for (int nt = 0; nt < 4; nt++) {
            int j = wn * 32 + nt * 8 + (l & 3) * 2;
            int e = j >> 4;
            float* a4 = acc[mt][nt];
            float s0v = g_c[(size_t)r0 * N_EXP + e];
            float s1v = g_c[(size_t)(r0 + 8) * N_EXP + e];
            __half2 h0 = __floats2half2_rn(a4[0] * s0v, a4[1] * s0v);
            __half2 h1 = __floats2half2_rn(a4[2] * s1v, a4[3] * s1v);
            *reinterpret_cast<uint32_t*>(g_xe + (size_t)r0 * K2 + D_MODEL + j) = h2u(h0);
            *reinterpret_cast<uint32_t*>(g_xe + (size_t)(r0 + 8) * K2 + D_MODEL + j) = h2u(h1);
        }
    }
}

// ---------------------------------------------------------------------------
// gemm_main: out[8192,1024] = xe @ W2^T + bias. CTA 128x128, BK=64, 3-stage,
// 8 warps (2M x 4N, warp tile 64x32), 2 CTAs/SM. grid (8, 64) = 512.
// ---------------------------------------------------------------------------
#define MST_A 16384u                  // 128*64*2
#define MST_B 16384u
#define MST   (MST_A + MST_B)         // 32768
#define MAIN_SMEM (3 * MST)           // 98304

__global__ __launch_bounds__(256, 2)
void gemm_main(const float* __restrict__ b_base, float* __restrict__ out) {
    extern __shared__ __align__(16) char ms[];
    const uint32_t s0 = smem_u32(ms);
    const int tid = threadIdx.x, l = tid & 31, wid = tid >> 5;
    const int wm = wid >> 2, wn = wid & 3;
    const int m0 = blockIdx.y * 128, n0 = blockIdx.x * 128;

    float acc[4][4][4];
#pragma unroll
    for (int i = 0; i < 4; i++)
#pragma unroll
        for (int j = 0; j < 4; j++)
#pragma unroll
            for (int k = 0; k < 4; k++) acc[i][j][k] = 0.f;

    auto load_tile = [&](int st, int kt) {
        const uint32_t base = s0 + st * MST;
#pragma unroll
        for (int p = 0; p < 4; p++) {   // A: 128 rows x 8 chunks = 1024 cp16
            int cid = tid + p * 256;
            int r = cid >> 3, c = cid & 7;
            cp16(base + SW64(r, c), g_xe + (size_t)(m0 + r) * K2 + kt + c * 8);
        }
#pragma unroll
        for (int p = 0; p < 4; p++) {   // B: 128 rows x 8 chunks = 1024 cp16
            int cid = tid + p * 256;
            int r = cid >> 3, c = cid & 7;
            cp16(base + MST_A + SW64(r, c), g_w2 + (size_t)(n0 + r) * K2 + kt + c * 8);
        }
    };

    load_tile(0, 0); cp_commit();
    load_tile(1, 64); cp_commit();

    const int NIT = K2 / 64;            // 18
    for (int it = 0; it < NIT; it++) {
        const int st = it % 3;
        if (it == NIT - 1) cp_wait<0>(); else cp_wait<1>();
        __syncthreads();
        if (it + 2 < NIT) { load_tile((it + 2) % 3, (it + 2) * 64); cp_commit(); }

        const uint32_t aBase = s0 + st * MST;
        const uint32_t bBase = aBase + MST_A;
#pragma unroll
        for (int ks = 0; ks < 4; ks++) {
            uint32_t af[4][4];
#pragma unroll
            for (int mt = 0; mt < 4; mt++) {
                int row = wm * 64 + mt * 16 + (l & 15);
                int ch = ks * 2 + (l >> 4);
                ldm4(af[mt], aBase + SW64(row, ch));
            }
#pragma unroll
            for (int q = 0; q < 2; q++) {
                uint32_t bf[4];
                int rn = wn * 32 + q * 16 + ((l >> 4) << 3) + (l & 7);
                int ch = ks * 2 + ((l >> 3) & 1);
                ldm4(bf, bBase + SW64(rn, ch));
#pragma unroll
                for (int mt = 0; mt < 4; mt++) {
                    mma16816(acc[mt][q * 2],     af[mt], bf);
                    mma16816(acc[mt][q * 2 + 1], af[mt], bf + 2);
                }
            }
        }
        __syncthreads();
    }

    // epilogue: + bias, write-only
#pragma unroll
    for (int mt = 0; mt < 4; mt++) {
        int r0 = m0 + wm * 64 + mt * 16 + (l >> 2);
#pragma unroll
        for (int nt = 0; nt < 4; nt++) {
            int j = n0 + wn * 32 + nt * 8 + (l & 3) * 2;
            float* a4 = acc[mt][nt];
            float2 bb = *reinterpret_cast<const float2*>(b_base + j);
            *reinterpret_cast<float2*>(out + (size_t)r0 * D_MODEL + j) =
                make_float2(a4[0] + bb.x, a4[1] + bb.y);
            *reinterpret_cast<float2*>(out + (size_t)(r0 + 8) * D_MODEL + j) =
                make_float2(a4[2] + bb.x, a4[3] + bb.y);
        }
    }
}

// ---------------------------------------------------------------------------
extern "C" void kernel_launch(void* const* d_in, const int* in_sizes, int n_in,
                              void* d_out, int out_size) {
    const float* x      = (const float*)d_in[0];
    const float* W_gate = (const float*)d_in[1];
    const float* A      = (const float*)d_in[2];
    const float* Bmat   = (const float*)d_in[3];
    const float* W_base = (const float*)d_in[4];
    const float* b_base = (const float*)d_in[5];
    float* out = (float*)d_out;

    cudaFuncSetAttribute(gemm_h, cudaFuncAttributeMaxDynamicSharedMemorySize, H_SMEM);
    cudaFuncSetAttribute(gemm_main, cudaFuncAttributeMaxDynamicSharedMemorySize, MAIN_SMEM);

    pack_gate<<<N_TOK / 32, 256>>>(x, W_gate);
    pack_at<<<(H_COLS * D_MODEL + 255) / 256, 256>>>(A);
    pack_w2<<<(D_MODEL * K2 + 255) / 256, 256>>>(W_base, Bmat);

    gemm_h<<<N_TOK / 32, 128, H_SMEM>>>();

    gemm_main<<<dim3(D_MODEL / 128, N_TOK / 128), 256, MAIN_SMEM>>>(b_base, out);
}

// round 11
// speedup vs baseline: 8.7300x; 1.0909x over previous
#include <cuda_runtime.h>
#include <cuda_fp16.h>
#include <cstdint>
#include <math.h>

#define N_TOK   8192
#define D_MODEL 1024
#define N_EXP   8
#define RANK    16
#define H_COLS  128
#define K2      (D_MODEL + H_COLS)   // 1152 concatenated K

// ---------------- device scratch (no-alloc rule) ----------------
__device__ __align__(16) __half g_xe[N_TOK * K2];        // [x | c*h] fp16, row stride 1152
__device__ __align__(16) __half g_w2[D_MODEL * K2];      // [Wbase^T ; B] fp16: row d, col k
__device__ __align__(16) __half g_at[H_COLS * D_MODEL];  // A^T fp16: [er][d]
__device__ __align__(16) float  g_c[N_TOK * N_EXP];      // dense combine weights

// ---------------- asm helpers (legal at compute_103) ----------------
__device__ __forceinline__ uint32_t smem_u32(const void* p) {
    uint32_t a;
    asm("{ .reg .u64 t; cvta.to.shared.u64 t, %1; cvt.u32.u64 %0, t; }" : "=r"(a) : "l"(p));
    return a;
}
__device__ __forceinline__ void cp16(uint32_t s, const void* g) {
    asm volatile("cp.async.cg.shared.global [%0], [%1], 16;" :: "r"(s), "l"(g));
}
__device__ __forceinline__ void cp_commit() {
    asm volatile("cp.async.commit_group;" ::: "memory");
}
template<int N> __device__ __forceinline__ void cp_wait() {
    asm volatile("cp.async.wait_group %0;" :: "n"(N) : "memory");
}
__device__ __forceinline__ void ldm4(uint32_t (&r)[4], uint32_t a) {
    asm volatile("ldmatrix.sync.aligned.m8n8.x4.shared.b16 {%0,%1,%2,%3}, [%4];"
        : "=r"(r[0]), "=r"(r[1]), "=r"(r[2]), "=r"(r[3]) : "r"(a));
}
__device__ __forceinline__ void mma16816(float* c, const uint32_t* a, const uint32_t* b) {
    asm volatile("mma.sync.aligned.m16n8k16.row.col.f32.f16.f16.f32 "
        "{%0,%1,%2,%3}, {%4,%5,%6,%7}, {%8,%9}, {%0,%1,%2,%3};"
        : "+f"(c[0]), "+f"(c[1]), "+f"(c[2]), "+f"(c[3])
        : "r"(a[0]), "r"(a[1]), "r"(a[2]), "r"(a[3]), "r"(b[0]), "r"(b[1]));
}
__device__ __forceinline__ uint32_t h2u(__half2 h) { return *reinterpret_cast<uint32_t*>(&h); }

// 128B-row swizzle (64 halves/row, 8 x 16B chunks): chunk' = c ^ (r&7)
#define SW64(r, c) ((uint32_t)((r) * 128 + (((c) ^ ((r) & 7)) << 4)))

// ---------------------------------------------------------------------------
// Fused pack x -> fp16 (into xe[:,0:1024]) + fp32 gate -> dense combine g_c
// ---------------------------------------------------------------------------
__global__ __launch_bounds__(256)
void pack_gate(const float* __restrict__ x, const float* __restrict__ Wg) {
    __shared__ float sWg[N_EXP][D_MODEL];          // 32 KB
    const int tid = threadIdx.x, l = tid & 31, wid = tid >> 5;

#pragma unroll
    for (int i = 0; i < 8; i++) {
        int f4 = tid + i * 256;
        reinterpret_cast<float4*>(&sWg[0][0])[f4] =
            reinterpret_cast<const float4*>(Wg)[f4];
    }
    __syncthreads();

    const int t0 = blockIdx.x * 32 + wid * 4;
    float acc[4][N_EXP];
#pragma unroll
    for (int t = 0; t < 4; t++)
#pragma unroll
        for (int e = 0; e < N_EXP; e++) acc[t][e] = 0.f;

#pragma unroll
    for (int i = 0; i < 8; i++) {
        const int k = i * 128 + l * 4;
        float4 wv[N_EXP];
#pragma unroll
        for (int e = 0; e < N_EXP; e++)
            wv[e] = *reinterpret_cast<const float4*>(&sWg[e][k]);
#pragma unroll
        for (int t = 0; t < 4; t++) {
            float4 xv = *reinterpret_cast<const float4*>(x + (size_t)(t0 + t) * D_MODEL + k);
            uint2 u;
            u.x = h2u(__floats2half2_rn(xv.x, xv.y));
            u.y = h2u(__floats2half2_rn(xv.z, xv.w));
            *reinterpret_cast<uint2*>(g_xe + (size_t)(t0 + t) * K2 + k) = u;
#pragma unroll
            for (int e = 0; e < N_EXP; e++) {
                acc[t][e] = fmaf(xv.x, wv[e].x, acc[t][e]);
                acc[t][e] = fmaf(xv.y, wv[e].y, acc[t][e]);
                acc[t][e] = fmaf(xv.z, wv[e].z, acc[t][e]);
                acc[t][e] = fmaf(xv.w, wv[e].w, acc[t][e]);
            }
        }
    }

#pragma unroll
    for (int o = 16; o; o >>= 1)
#pragma unroll
        for (int t = 0; t < 4; t++)
#pragma unroll
            for (int e = 0; e < N_EXP; e++)
                acc[t][e] += __shfl_xor_sync(0xffffffffu, acc[t][e], o);

    if (l == 0) {
#pragma unroll
        for (int t = 0; t < 4; t++) {
            float* lg = acc[t];
            int i0 = 0; float v0 = lg[0];
#pragma unroll
            for (int e = 1; e < N_EXP; e++) if (lg[e] > v0) { v0 = lg[e]; i0 = e; }
            int i1 = -1; float v1 = -1e30f;
#pragma unroll
            for (int e = 0; e < N_EXP; e++) if (e != i0 && lg[e] > v1) { v1 = lg[e]; i1 = e; }
            float e1 = expf(v1 - v0);
            float inv = 1.0f / (1.0f + e1);
#pragma unroll
            for (int e = 0; e < N_EXP; e++)
                g_c[(size_t)(t0 + t) * N_EXP + e] = (e == i0) ? inv : (e == i1) ? e1 * inv : 0.f;
        }
    }
}

// ---------------------------------------------------------------------------
// Merged weight pack: g_w2 ([Wbase^T ; B]) + g_at (A^T) in one launch
// ---------------------------------------------------------------------------
#define W2_ELEMS (D_MODEL * K2)
#define AT_ELEMS (H_COLS * D_MODEL)
__global__ void pack_weights(const float* __restrict__ Wb, const float* __restrict__ Bmat,
                             const float* __restrict__ A) {
    int idx = blockIdx.x * blockDim.x + threadIdx.x;
    if (idx < W2_ELEMS) {
        int d = idx / K2, k = idx - d * K2;
        float v = (k < D_MODEL) ? Wb[(size_t)d * D_MODEL + k]
                                : Bmat[(size_t)(k - D_MODEL) * D_MODEL + d];
        g_w2[idx] = __float2half_rn(v);
    } else if (idx < W2_ELEMS + AT_ELEMS) {
        int t = idx - W2_ELEMS;
        int er = t >> 10, d = t & 1023;
        int e = er >> 4, r = er & 15;
        g_at[t] = __float2half_rn(A[((size_t)e * D_MODEL + d) * RANK + r]);
    }
}

// ---------------------------------------------------------------------------
// gemm_h: h[8192,128] = xe[:, :1024] @ A^T ; epilogue *combine -> fp16 -> xe[:,1024:]
// CTA 32x128, 128 threads (4 warps, warp tile 32x32), BK=64, 3-stage. grid 256.
// ---------------------------------------------------------------------------
#define HST_A 4096u                   // 32*64*2
#define HST_B 16384u                  // 128*64*2
#define HST   (HST_A + HST_B)         // 20480
#define H_SMEM (3 * HST)              // 61440

__global__ __launch_bounds__(128, 3)
void gemm_h() {
    extern __shared__ __align__(16) char hs[];
    const uint32_t s0 = smem_u32(hs);
    const int tid = threadIdx.x, l = tid & 31, wn = tid >> 5;   // 4 warps: 1M x 4N
    const int m0 = blockIdx.x * 32;

    float acc[2][4][4];
#pragma unroll
    for (int i = 0; i < 2; i++)
#pragma unroll
        for (int j = 0; j < 4; j++)
#pragma unroll
            for (int k = 0; k < 4; k++) acc[i][j][k] = 0.f;

    auto load_tile = [&](int st, int kt) {
        const uint32_t base = s0 + st * HST;
#pragma unroll
        for (int p = 0; p < 2; p++) {
            int cid = tid + p * 128;
            int r = cid >> 3, c = cid & 7;
            cp16(base + SW64(r, c), g_xe + (size_t)(m0 + r) * K2 + kt + c * 8);
        }
#pragma unroll
        for (int p = 0; p < 8; p++) {
            int cid = tid + p * 128;
            int r = cid >> 3, c = cid & 7;
            cp16(base + HST_A + SW64(r, c), g_at + (size_t)r * D_MODEL + kt + c * 8);
        }
    };

    load_tile(0, 0); cp_commit();
    load_tile(1, 64); cp_commit();

    const int NIT = D_MODEL / 64;       // 16
    for (int it = 0; it < NIT; it++) {
        const int st = it % 3;
        if (it == NIT - 1) cp_wait<0>(); else cp_wait<1>();
        __syncthreads();
        if (it + 2 < NIT) { load_tile((it + 2) % 3, (it + 2) * 64); cp_commit(); }

        const uint32_t aBase = s0 + st * HST;
        const uint32_t bBase = aBase + HST_A;
#pragma unroll
        for (int ks = 0; ks < 4; ks++) {
            uint32_t af[2][4];
#pragma unroll
            for (int mt = 0; mt < 2; mt++) {
                int row = mt * 16 + (l & 15);
                int ch = ks * 2 + (l >> 4);
                ldm4(af[mt], aBase + SW64(row, ch));
            }
#pragma unroll
            for (int q = 0; q < 2; q++) {
                uint32_t bf[4];
                int rn = wn * 32 + q * 16 + ((l >> 4) << 3) + (l & 7);
                int ch = ks * 2 + ((l >> 3) & 1);
                ldm4(bf, bBase + SW64(rn, ch));
#pragma unroll
                for (int mt = 0; mt < 2; mt++) {
                    mma16816(acc[mt][q * 2],     af[mt], bf);
                    mma16816(acc[mt][q * 2 + 1], af[mt], bf + 2);
                }
            }
        }
        __syncthreads();
    }

#pragma unroll
    for (int mt = 0; mt < 2; mt++) {
        int r0 = m0 + mt * 16 + (l >> 2);
#pragma unroll
        for (int nt = 0; nt < 4; nt++) {
            int j = wn * 32 + nt * 8 + (l & 3) * 2;
            int e = j >> 4;
            float* a4 = acc[mt][nt];
            float s0v = g_c[(size_t)r0 * N_EXP + e];
            float s1v = g_c[(size_t)(r0 + 8) * N_EXP + e];
            __half2 h0 = __floats2half2_rn(a4[0] * s0v, a4[1] * s0v);
            __half2 h1 = __floats2half2_rn(a4[2] * s1v, a4[3] * s1v);
            *reinterpret_cast<uint32_t*>(g_xe + (size_t)r0 * K2 + D_MODEL + j) = h2u(h0);
            *reinterpret_cast<uint32_t*>(g_xe + (size_t)(r0 + 8) * K2 + D_MODEL + j) = h2u(h1);
        }
    }
}

// ---------------------------------------------------------------------------
// gemm_main: out[8192,1024] = xe @ W2^T + bias.
// CTA 128x128, 128 threads (4 warps, warp tile 64x64 -> 4.0 MMA/LDSM),
// BK=64, 3-stage cp.async, 2 CTAs/SM. grid (8, 64) = 512.
// ---------------------------------------------------------------------------
#define MST_A 16384u                  // 128*64*2
#define MST_B 16384u
#define MST   (MST_A + MST_B)         // 32768
#define MAIN_SMEM (3 * MST)           // 98304

__global__ __launch_bounds__(128, 2)
void gemm_main(const float* __restrict__ b_base, float* __restrict__ out) {
    extern __shared__ __align__(16) char ms[];
    const uint32_t s0 = smem_u32(ms);
    const int tid = threadIdx.x, l = tid & 31, wid = tid >> 5;
    const int wm = wid >> 1, wn = wid & 1;          // 2x2 warp grid, 64x64 tiles
    const int m0 = blockIdx.y * 128, n0 = blockIdx.x * 128;

    float acc[4][8][4];
#pragma unroll
    for (int i = 0; i < 4; i++)
#pragma unroll
        for (int j = 0; j < 8; j++)
#pragma unroll
            for (int k = 0; k < 4; k++) acc[i][j][k] = 0.f;

    auto load_tile = [&](int st, int kt) {
        const uint32_t base = s0 + st * MST;
#pragma unroll
        for (int p = 0; p < 8; p++) {   // A: 128 rows x 8 chunks = 1024 cp16
            int cid = tid + p * 128;
            int r = cid >> 3, c = cid & 7;
            cp16(base + SW64(r, c), g_xe + (size_t)(m0 + r) * K2 + kt + c * 8);
        }
#pragma unroll
        for (int p = 0; p < 8; p++) {   // B: 128 rows x 8 chunks = 1024 cp16
            int cid = tid + p * 128;
            int r = cid >> 3, c = cid & 7;
            cp16(base + MST_A + SW64(r, c), g_w2 + (size_t)(n0 + r) * K2 + kt + c * 8);
        }
    };

    load_tile(0, 0); cp_commit();
    load_tile(1, 64); cp_commit();

    const int NIT = K2 / 64;            // 18
    for (int it = 0; it < NIT; it++) {
        const int st = it % 3;
        if (it == NIT - 1) cp_wait<0>(); else cp_wait<1>();
        __syncthreads();
        if (it + 2 < NIT) { load_tile((it + 2) % 3, (it + 2) * 64); cp_commit(); }

        const uint32_t aBase = s0 + st * MST;
        const uint32_t bBase = aBase + MST_A;
#pragma unroll
        for (int ks = 0; ks < 4; ks++) {
            uint32_t af[4][4];
#pragma unroll
            for (int mt = 0; mt < 4; mt++) {
                int row = wm * 64 + mt * 16 + (l & 15);
                int ch = ks * 2 + (l >> 4);
                ldm4(af[mt], aBase + SW64(row, ch));
            }
            uint32_t bf[4][4];
#pragma unroll
            for (int q = 0; q < 4; q++) {
                int rn = wn * 64 + q * 16 + ((l >> 4) << 3) + (l & 7);
                int ch = ks * 2 + ((l >> 3) & 1);
                ldm4(bf[q], bBase + SW64(rn, ch));
            }
#pragma unroll
            for (int mt = 0; mt < 4; mt++)
#pragma unroll
                for (int q = 0; q < 4; q++) {
                    mma16816(acc[mt][q * 2],     af[mt], bf[q]);
                    mma16816(acc[mt][q * 2 + 1], af[mt], bf[q] + 2);
                }
        }
        __syncthreads();
    }

    // epilogue: + bias, write-only
#pragma unroll
    for (int mt = 0; mt < 4; mt++) {
        int r0 = m0 + wm * 64 + mt * 16 + (l >> 2);
#pragma unroll
        for (int nt = 0; nt < 8; nt++) {
            int j = n0 + wn * 64 + nt * 8 + (l & 3) * 2;
            float* a4 = acc[mt][nt];
            float2 bb = *reinterpret_cast<const float2*>(b_base + j);
            *reinterpret_cast<float2*>(out + (size_t)r0 * D_MODEL + j) =
                make_float2(a4[0] + bb.x, a4[1] + bb.y);
            *reinterpret_cast<float2*>(out + (size_t)(r0 + 8) * D_MODEL + j) =
                make_float2(a4[2] + bb.x, a4[3] + bb.y);
        }
    }
}

// ---------------------------------------------------------------------------
extern "C" void kernel_launch(void* const* d_in, const int* in_sizes, int n_in,
                              void* d_out, int out_size) {
    const float* x      = (const float*)d_in[0];
    const float* W_gate = (const float*)d_in[1];
    const float* A      = (const float*)d_in[2];
    const float* Bmat   = (const float*)d_in[3];
    const float* W_base = (const float*)d_in[4];
    const float* b_base = (const float*)d_in[5];
    float* out = (float*)d_out;

    cudaFuncSetAttribute(gemm_h, cudaFuncAttributeMaxDynamicSharedMemorySize, H_SMEM);
    cudaFuncSetAttribute(gemm_main, cudaFuncAttributeMaxDynamicSharedMemorySize, MAIN_SMEM);

    pack_gate<<<N_TOK / 32, 256>>>(x, W_gate);
    pack_weights<<<(W2_ELEMS + AT_ELEMS + 255) / 256, 256>>>(W_base, Bmat, A);

    gemm_h<<<N_TOK / 32, 128, H_SMEM>>>();

    gemm_main<<<dim3(D_MODEL / 128, N_TOK / 128), 128, MAIN_SMEM>>>(b_base, out);
}